// round 1
// baseline (speedup 1.0000x reference)
#include <cuda_runtime.h>
#include <math.h>

// ---------------------------------------------------------------------------
// MultiScaleHyperGenerator: 7-layer grouped 3x3 conv chain, B=16 groups.
//   head : [16,3,256,256] (zero-pad 7)  -> [16,64,268,268], leaky_relu(0.02)
//   body0..4 : 64->64 VALID 3x3, leaky_relu     268->266->264->262->260->258
//   tail : 64->3 VALID 3x3, tanh        -> [16,3,256,256]
// norm_weight folds to scalars: out = cw*conv(x,w) + cb*b
// ---------------------------------------------------------------------------

#define BATCH 16
#define NFEAT 64

// ping-pong scratch: [16, 64, 268, 268] floats = 294 MB each
__device__ float g_buf0[16u * 64u * 268u * 268u];
__device__ float g_buf1[16u * 64u * 268u * 268u];

// ---------------------------------------------------------------------------
// Head: IC=3 with implicit zero-padding of 7 around the 256x256 noise.
// Block: 256 thr = 32x8 output tile, 16 out-channels per block.
// ---------------------------------------------------------------------------
__global__ __launch_bounds__(256)
void head_kernel(const float* __restrict__ noise,   // [16,3,256,256]
                 const float* __restrict__ hw,      // [16,64,3,3,3]
                 const float* __restrict__ hb,      // [16,64]
                 float* __restrict__ out,           // [16,64,268,268]
                 float cw, float cb)
{
    const int Sout = 268;
    int b   = blockIdx.z >> 2;
    int oc0 = (blockIdx.z & 3) << 4;
    int tx0 = blockIdx.x * 32, ty0 = blockIdx.y * 8;
    int tid = threadIdx.x, tx = tid & 31, ty = tid >> 5;

    __shared__ __align__(16) float ws[3 * 9 * 16];  // [ic][k][oc]
    __shared__ float xs[3 * 10 * 34];                // [ic][10][34]

    for (int i = tid; i < 3 * 144; i += 256) {
        int oc = i & 15, k = (i >> 4) % 9, ic = i / 144;
        ws[i] = hw[((b * 64 + oc0 + oc) * 3 + ic) * 9 + k];
    }
    for (int i = tid; i < 3 * 340; i += 256) {
        int ic = i / 340, rem = i % 340, r = rem / 34, c = rem % 34;
        int gy = ty0 + r - 7, gx = tx0 + c - 7;
        float v = 0.f;
        if (gy >= 0 && gy < 256 && gx >= 0 && gx < 256)
            v = noise[((size_t)(b * 3 + ic) * 256 + gy) * 256 + gx];
        xs[i] = v;
    }
    __syncthreads();

    float acc[16];
#pragma unroll
    for (int o = 0; o < 16; o++) acc[o] = 0.f;

#pragma unroll
    for (int ic = 0; ic < 3; ic++) {
        const float* xp = xs + ic * 340 + ty * 34 + tx;
        float xv[9];
#pragma unroll
        for (int ky = 0; ky < 3; ky++)
#pragma unroll
            for (int kx = 0; kx < 3; kx++)
                xv[ky * 3 + kx] = xp[ky * 34 + kx];
        const float4* wp = (const float4*)(ws + ic * 144);
#pragma unroll
        for (int k = 0; k < 9; k++) {
#pragma unroll
            for (int q = 0; q < 4; q++) {
                float4 w4 = wp[k * 4 + q];
                acc[q * 4 + 0] = fmaf(xv[k], w4.x, acc[q * 4 + 0]);
                acc[q * 4 + 1] = fmaf(xv[k], w4.y, acc[q * 4 + 1]);
                acc[q * 4 + 2] = fmaf(xv[k], w4.z, acc[q * 4 + 2]);
                acc[q * 4 + 3] = fmaf(xv[k], w4.w, acc[q * 4 + 3]);
            }
        }
    }

    int ox = tx0 + tx, oy = ty0 + ty;
    if (ox < Sout && oy < Sout) {
        size_t obase = ((size_t)(b * 64 + oc0)) * Sout * Sout + (size_t)oy * Sout + ox;
#pragma unroll
        for (int o = 0; o < 16; o++) {
            float v = acc[o] * cw + hb[b * 64 + oc0 + o] * cb;
            v = v > 0.f ? v : 0.02f * v;
            out[obase + (size_t)o * Sout * Sout] = v;
        }
    }
}

// ---------------------------------------------------------------------------
// Body: IC=OC=64, VALID, leaky_relu. 256 thr = 32x8 tile, 16 oc per block.
// All 16x64x9 weights staged in smem [ic][k][oc] (36 KB); input staged
// 8 ic-planes at a time (10x34 tiles, 10.6 KB). Total 47.7 KB static smem.
// ---------------------------------------------------------------------------
__global__ __launch_bounds__(256)
void body_kernel(const float* __restrict__ in,     // [16,64,Sin,Sin]
                 const float* __restrict__ w,      // [16,64,64,3,3]
                 const float* __restrict__ bias,   // [16,64]
                 float* __restrict__ out,          // [16,64,Sout,Sout]
                 int Sin, float cw, float cb)
{
    const int Sout = Sin - 2;
    int b   = blockIdx.z >> 2;
    int oc0 = (blockIdx.z & 3) << 4;
    int tx0 = blockIdx.x * 32, ty0 = blockIdx.y * 8;
    int tid = threadIdx.x, tx = tid & 31, ty = tid >> 5;

    __shared__ __align__(16) float ws[64 * 9 * 16]; // [ic][k][oc]  36 KB
    __shared__ float xs[8 * 340];                    // 8 planes [10][34]

    for (int i = tid; i < 64 * 144; i += 256) {
        int oc = i & 15, k = (i >> 4) % 9, ic = i / 144;
        ws[i] = w[((b * 64 + oc0 + oc) * 64 + ic) * 9 + k];
    }

    float acc[16];
#pragma unroll
    for (int o = 0; o < 16; o++) acc[o] = 0.f;

    const float* inb = in + (size_t)b * 64 * Sin * Sin;

    for (int ics = 0; ics < 64; ics += 8) {
        __syncthreads();
        for (int i = tid; i < 8 * 340; i += 256) {
            int icl = i / 340, rem = i % 340, r = rem / 34, c = rem % 34;
            int gy = ty0 + r, gx = tx0 + c;
            float v = 0.f;
            if (gy < Sin && gx < Sin)
                v = inb[(size_t)(ics + icl) * Sin * Sin + (size_t)gy * Sin + gx];
            xs[i] = v;
        }
        __syncthreads();

#pragma unroll
        for (int icl = 0; icl < 8; icl++) {
            const float* xp = xs + icl * 340 + ty * 34 + tx;
            float xv[9];
#pragma unroll
            for (int ky = 0; ky < 3; ky++)
#pragma unroll
                for (int kx = 0; kx < 3; kx++)
                    xv[ky * 3 + kx] = xp[ky * 34 + kx];
            const float4* wp = (const float4*)(ws + (ics + icl) * 144);
#pragma unroll
            for (int k = 0; k < 9; k++) {
#pragma unroll
                for (int q = 0; q < 4; q++) {
                    float4 w4 = wp[k * 4 + q];
                    acc[q * 4 + 0] = fmaf(xv[k], w4.x, acc[q * 4 + 0]);
                    acc[q * 4 + 1] = fmaf(xv[k], w4.y, acc[q * 4 + 1]);
                    acc[q * 4 + 2] = fmaf(xv[k], w4.z, acc[q * 4 + 2]);
                    acc[q * 4 + 3] = fmaf(xv[k], w4.w, acc[q * 4 + 3]);
                }
            }
        }
    }

    int ox = tx0 + tx, oy = ty0 + ty;
    if (ox < Sout && oy < Sout) {
        size_t obase = ((size_t)(b * 64 + oc0)) * Sout * Sout + (size_t)oy * Sout + ox;
#pragma unroll
        for (int o = 0; o < 16; o++) {
            float v = acc[o] * cw + bias[b * 64 + oc0 + o] * cb;
            v = v > 0.f ? v : 0.02f * v;
            out[obase + (size_t)o * Sout * Sout] = v;
        }
    }
}

// ---------------------------------------------------------------------------
// Tail: IC=64, OC=3, tanh. 256 thr = 32x8 tile, all 3 oc in one block.
// ---------------------------------------------------------------------------
__global__ __launch_bounds__(256)
void tail_kernel(const float* __restrict__ in,     // [16,64,258,258]
                 const float* __restrict__ w,      // [16,3,64,3,3]
                 const float* __restrict__ bias,   // [16,3]
                 float* __restrict__ out,          // [16,3,256,256]
                 float cw, float cb)
{
    const int Sin = 258, Sout = 256;
    int b   = blockIdx.z;
    int tx0 = blockIdx.x * 32, ty0 = blockIdx.y * 8;
    int tid = threadIdx.x, tx = tid & 31, ty = tid >> 5;

    __shared__ float ws[64 * 9 * 3];  // [ic][k][oc]
    __shared__ float xs[8 * 340];

    for (int i = tid; i < 64 * 27; i += 256) {
        int oc = i % 3, k = (i / 3) % 9, ic = i / 27;
        ws[i] = w[((b * 3 + oc) * 64 + ic) * 9 + k];
    }

    float acc[3] = {0.f, 0.f, 0.f};
    const float* inb = in + (size_t)b * 64 * Sin * Sin;

    for (int ics = 0; ics < 64; ics += 8) {
        __syncthreads();
        for (int i = tid; i < 8 * 340; i += 256) {
            int icl = i / 340, rem = i % 340, r = rem / 34, c = rem % 34;
            int gy = ty0 + r, gx = tx0 + c;
            float v = 0.f;
            if (gy < Sin && gx < Sin)
                v = inb[(size_t)(ics + icl) * Sin * Sin + (size_t)gy * Sin + gx];
            xs[i] = v;
        }
        __syncthreads();

#pragma unroll
        for (int icl = 0; icl < 8; icl++) {
            const float* xp = xs + icl * 340 + ty * 34 + tx;
            float xv[9];
#pragma unroll
            for (int ky = 0; ky < 3; ky++)
#pragma unroll
                for (int kx = 0; kx < 3; kx++)
                    xv[ky * 3 + kx] = xp[ky * 34 + kx];
            const float* wp = ws + (ics + icl) * 27;
#pragma unroll
            for (int k = 0; k < 9; k++) {
#pragma unroll
                for (int o = 0; o < 3; o++)
                    acc[o] = fmaf(xv[k], wp[k * 3 + o], acc[o]);
            }
        }
    }

    int ox = tx0 + tx, oy = ty0 + ty;
    if (ox < Sout && oy < Sout) {
        size_t obase = ((size_t)(b * 3)) * Sout * Sout + (size_t)oy * Sout + ox;
#pragma unroll
        for (int o = 0; o < 3; o++) {
            float v = tanhf(acc[o] * cw + bias[b * 3 + o] * cb);
            out[obase + (size_t)o * Sout * Sout] = v;
        }
    }
}

// ---------------------------------------------------------------------------
extern "C" void kernel_launch(void* const* d_in, const int* in_sizes, int n_in,
                              void* d_out, int out_size)
{
    const float* noise  = (const float*)d_in[0];
    const float* head_w = (const float*)d_in[1];
    const float* head_b = (const float*)d_in[2];
    const float* body_w = (const float*)d_in[3];
    const float* body_b = (const float*)d_in[4];
    const float* tail_w = (const float*)d_in[5];
    const float* tail_b = (const float*)d_in[6];
    float* out = (float*)d_out;

    float *buf0 = nullptr, *buf1 = nullptr;
    cudaGetSymbolAddress((void**)&buf0, g_buf0);
    cudaGetSymbolAddress((void**)&buf1, g_buf1);

    const double lr_gain = sqrt(2.0 / (1.0 + 0.02 * 0.02));
    const float cw_head = (float)(lr_gain / sqrt(27.0));
    const float cb_head = (float)(1.0 / sqrt(3.0));
    const float cw_body = (float)(lr_gain / 24.0);
    const float cb_body = 0.125f;
    const float cw_tail = (float)((5.0 / 3.0) / 24.0);
    const float cb_tail = 0.125f;

    // head: noise -> buf0 (268)
    {
        dim3 grid((268 + 31) / 32, (268 + 7) / 8, BATCH * 4);
        head_kernel<<<grid, 256>>>(noise, head_w, head_b, buf0, cw_head, cb_head);
    }

    // 5 body layers, ping-pong
    float* src = buf0;
    float* dst = buf1;
    int Sin = 268;
    for (int i = 0; i < 5; i++) {
        int Sout = Sin - 2;
        dim3 grid((Sout + 31) / 32, (Sout + 7) / 8, BATCH * 4);
        const float* wi = body_w + (size_t)i * 16 * 64 * 64 * 9;
        const float* bi = body_b + (size_t)i * 16 * 64;
        body_kernel<<<grid, 256>>>(src, wi, bi, dst, Sin, cw_body, cb_body);
        float* t = src; src = dst; dst = t;
        Sin = Sout;
    }

    // tail: src(258) -> out (256)
    {
        dim3 grid(256 / 32, 256 / 8, BATCH);
        tail_kernel<<<grid, 256>>>(src, tail_w, tail_b, out, cw_tail, cb_tail);
    }
}